// round 15
// baseline (speedup 1.0000x reference)
#include <cuda_runtime.h>
#include <cuda_fp16.h>
#include <math.h>
#include <stdint.h>

// ---------------------------------------------------------------------------
// MolecularGNN: 3x GCNConv(+BN+ReLU) -> global mean pool -> MLP head
// Bucketed single-pass CSR + split-fp16 HMMA GEMMs (KC=32, layer0 padded to 64).
// ---------------------------------------------------------------------------

#define N_NODES  100000
#define N_EDGES  3200000
#define N_GRAPHS 4096
#define BN_EPS   1e-5f
#define CAP      128         // slots per node; deg ~ Poisson(32), P(>128) ~ 0

// ---- scratch (device globals; allocation-free rule) -----------------------
__device__ __align__(256) int    g_ecnt  [N_NODES];
__device__ __align__(256) float  g_dinv  [N_NODES];
__device__ __align__(256) int    g_csr   [N_NODES * CAP];
__device__ __align__(256) __half g_xs    [N_NODES * 36];   // x * dinv (fp16)
__device__ __align__(256) float  g_t     [N_NODES * 64];   // aggregated x, padded to 64
__device__ __align__(256) __half g_xw    [N_NODES * 128];  // (h@W)*dinv (fp16)
__device__ __align__(256) float  g_bufB  [N_NODES * 128];  // h (fp32)
__device__ __align__(256) __half g_w0hi  [64 * 128];
__device__ __align__(256) __half g_w0lo  [64 * 128];
__device__ __align__(256) __half g_w1hi  [128 * 128];
__device__ __align__(256) __half g_w1lo  [128 * 128];
__device__ __align__(256) __half g_w2hi  [128 * 64];
__device__ __align__(256) __half g_w2lo  [128 * 64];
__device__ __align__(256) float  g_sums  [N_GRAPHS * 64];
__device__ __align__(256) float  g_cnt   [N_GRAPHS];

__device__ __forceinline__ void red_add_f32(float* p, float v) {
    asm volatile("red.global.add.f32 [%0], %1;" :: "l"(p), "f"(v) : "memory");
}

// ---- mma helpers ----------------------------------------------------------
__device__ __forceinline__ void ldsm4(uint32_t* r, const void* p) {
    uint32_t addr = (uint32_t)__cvta_generic_to_shared(p);
    asm volatile("ldmatrix.sync.aligned.m8n8.x4.shared.b16 {%0,%1,%2,%3}, [%4];"
        : "=r"(r[0]), "=r"(r[1]), "=r"(r[2]), "=r"(r[3]) : "r"(addr));
}
__device__ __forceinline__ void ldsm4t(uint32_t* r, const void* p) {
    uint32_t addr = (uint32_t)__cvta_generic_to_shared(p);
    asm volatile("ldmatrix.sync.aligned.m8n8.x4.trans.shared.b16 {%0,%1,%2,%3}, [%4];"
        : "=r"(r[0]), "=r"(r[1]), "=r"(r[2]), "=r"(r[3]) : "r"(addr));
}
__device__ __forceinline__ void mma16816(float* c, const uint32_t* a,
                                         uint32_t b0, uint32_t b1) {
    asm volatile("mma.sync.aligned.m16n8k16.row.col.f32.f16.f16.f32 "
        "{%0,%1,%2,%3}, {%4,%5,%6,%7}, {%8,%9}, {%0,%1,%2,%3};"
        : "+f"(c[0]), "+f"(c[1]), "+f"(c[2]), "+f"(c[3])
        : "r"(a[0]), "r"(a[1]), "r"(a[2]), "r"(a[3]), "r"(b0), "r"(b1));
}
__device__ __forceinline__ void split2(float a, float b, uint32_t& hi, uint32_t& lo) {
    __half h0 = __float2half_rn(a), h1 = __float2half_rn(b);
    __half l0 = __float2half_rn(a - __half2float(h0));
    __half l1 = __float2half_rn(b - __half2float(h1));
    __half2 ph = __halves2half2(h0, h1), pl = __halves2half2(l0, l1);
    hi = *reinterpret_cast<uint32_t*>(&ph);
    lo = *reinterpret_cast<uint32_t*>(&pl);
}

// ---- single-pass bucketed CSR fill (x4 ILP) + weight split (tail) ---------
__global__ void fill_wsplit_kernel(const int* __restrict__ src,
                                   const int* __restrict__ dst,
                                   const float* __restrict__ w0,
                                   const float* __restrict__ w1,
                                   const float* __restrict__ w2)
{
    if (blockIdx.x < 2048) {
        const int t = blockIdx.x * 256 + threadIdx.x;
        const int stride4 = 2048 * 256 * 4;
        for (int e4 = t * 4; e4 < N_EDGES; e4 += stride4) {   // N_EDGES % 4 == 0
            int4 d4 = *reinterpret_cast<const int4*>(dst + e4);
            int4 s4 = *reinterpret_cast<const int4*>(src + e4);
            int p0 = atomicAdd(&g_ecnt[d4.x], 1);
            int p1 = atomicAdd(&g_ecnt[d4.y], 1);
            int p2 = atomicAdd(&g_ecnt[d4.z], 1);
            int p3 = atomicAdd(&g_ecnt[d4.w], 1);
            if (p0 < CAP) g_csr[(size_t)d4.x * CAP + p0] = s4.x;
            if (p1 < CAP) g_csr[(size_t)d4.y * CAP + p1] = s4.y;
            if (p2 < CAP) g_csr[(size_t)d4.z * CAP + p2] = s4.z;
            if (p3 < CAP) g_csr[(size_t)d4.w * CAP + p3] = s4.w;
        }
    } else {
        int i = (blockIdx.x - 2048) * 256 + threadIdx.x;   // 0..32767
        if (i < 8192) {            // W0 padded to 64x128 (rows >= 36 zero)
            float v = (i < 36 * 128) ? w0[i] : 0.0f;
            __half h = __float2half_rn(v);
            g_w0hi[i] = h;
            g_w0lo[i] = __float2half_rn(v - __half2float(h));
        } else if (i < 8192 + 16384) {
            int j = i - 8192;
            float v = w1[j];
            __half h = __float2half_rn(v);
            g_w1hi[j] = h;
            g_w1lo[j] = __float2half_rn(v - __half2float(h));
        } else {
            int j = i - 8192 - 16384;   // < 8192
            float v = w2[j];
            __half h = __float2half_rn(v);
            g_w2hi[j] = h;
            g_w2lo[j] = __float2half_rn(v - __half2float(h));
        }
    }
}

// ---- dinv + x -> fp16*dinv ------------------------------------------------
__global__ void dinv_kernel(const float* __restrict__ x) {
    int i = blockIdx.x * blockDim.x + threadIdx.x;
    if (i < N_NODES) {
        float di = rsqrtf((float)g_ecnt[i] + 1.0f);
        g_dinv[i] = di;
        const float2* xr = reinterpret_cast<const float2*>(x + (size_t)i * 36);
        __half2* xo = reinterpret_cast<__half2*>(g_xs + (size_t)i * 36);
#pragma unroll
        for (int j = 0; j < 18; j++) {
            float2 v = xr[j];
            xo[j] = __floats2half2_rn(v.x * di, v.y * di);
        }
    }
}

// ---- layer-0 aggregation over 36-wide fp16 rows -> t[N][64] (padded) ------
__global__ void agg0_kernel() {
    const int tid  = threadIdx.x;
    const int lane = tid & 31;
    const int wid  = tid >> 5;
    const int node = blockIdx.x * 8 + wid;
    if (node >= N_NODES) return;

    const int beg = node * CAP;
    const int end = beg + g_ecnt[node];

    float a0 = 0.0f, a1 = 0.0f;
    const bool act = (lane < 18);

    auto gather = [&](int s) {
        if (act) {
            __half2 v = *reinterpret_cast<const __half2*>(g_xs + (size_t)s * 36 + lane * 2);
            float2 f = __half22float2(v);
            a0 += f.x; a1 += f.y;
        }
    };

    int b = beg;
    const int nfull = (end - beg) & ~31;
    for (; b < beg + nfull; b += 32) {
        int pk = g_csr[b + lane];
#pragma unroll 8
        for (int j = 0; j < 32; j++) {
            int s = __shfl_sync(0xffffffffu, pk, j);
            gather(s);
        }
    }
    if (b < end) {
        int e = b + lane;
        int ssrc = (e < end) ? g_csr[e] : 0;
        int cnt = end - b;
        for (int j = 0; j < cnt; j++) {
            int s = __shfl_sync(0xffffffffu, ssrc, j);
            gather(s);
        }
    }
    gather(node);   // self loop

    {
        float di = g_dinv[node];
        float2 o = act ? make_float2(a0 * di, a1 * di) : make_float2(0.f, 0.f);
        *reinterpret_cast<float2*>(g_t + (size_t)node * 64 + lane * 2) = o;
    }
}

// ---- split-fp16 tensor-core GEMM, KC=32, templated epilogue ---------------
// 256 threads (8 warps) x 128-row tile; 3-term Markidis.
template<int FIN, int FOUT, bool BN_EPI>
__global__ __launch_bounds__(256) void mma_gemm_kernel(
    const float* __restrict__ A,      // [N, FIN] fp32
    const __half* __restrict__ Bhi,   // [FIN, FOUT]
    const __half* __restrict__ Blo,
    float* __restrict__ OutF,
    __half* __restrict__ OutH,
    const float* __restrict__ bias,
    const float* __restrict__ bn_g, const float* __restrict__ bn_b,
    const float* __restrict__ bn_m, const float* __restrict__ bn_v)
{
    constexpr int KC = 32;
    constexpr int NF = FOUT / 8;
    __shared__ __half Ahi[128][KC + 8];
    __shared__ __half Alo[128][KC + 8];
    __shared__ __half Bhs[KC][FOUT + 8];
    __shared__ __half Bls[KC][FOUT + 8];
    __shared__ float s_sc [FOUT];
    __shared__ float s_shb[FOUT];

    const int tid  = threadIdx.x;
    const int lane = tid & 31;
    const int warp = tid >> 5;
    const int row0 = blockIdx.x * 128;

    if constexpr (BN_EPI) {
        if (tid < FOUT) {
            float sc = bn_g[tid] * rsqrtf(bn_v[tid] + BN_EPS);
            s_sc [tid] = sc;
            s_shb[tid] = sc * (bias[tid] - bn_m[tid]) + bn_b[tid];
        }
    }

    float acc[NF][4];
#pragma unroll
    for (int nf = 0; nf < NF; nf++)
#pragma unroll
        for (int j = 0; j < 4; j++) acc[nf][j] = 0.0f;

    const int wrow  = warp * 16;
    const int arow  = wrow + (lane & 15);
    const int acol8 = (lane >> 4) * 8;

    for (int kc = 0; kc < FIN; kc += KC) {
        __syncthreads();
        // stage A chunk (128 x 32 fp32 -> hi/lo)
        {
            constexpr int C4 = KC / 4;   // 8
            for (int i = tid; i < 128 * C4; i += 256) {
                int r = i / C4, c4 = i % C4;
                float4 v = make_float4(0.f, 0.f, 0.f, 0.f);
                if (row0 + r < N_NODES)
                    v = *reinterpret_cast<const float4*>(
                        A + (size_t)(row0 + r) * FIN + kc + c4 * 4);
                uint32_t h0, l0, h1, l1;
                split2(v.x, v.y, h0, l0);
                split2(v.z, v.w, h1, l1);
                uint2 uh = make_uint2(h0, h1), ul = make_uint2(l0, l1);
                *reinterpret_cast<uint2*>(&Ahi[r][c4 * 4]) = uh;
                *reinterpret_cast<uint2*>(&Alo[r][c4 * 4]) = ul;
            }
        }
        // stage B chunk (32 x FOUT, hi and lo)
        {
            constexpr int BV = FOUT / 8;
            for (int i = tid; i < KC * BV; i += 256) {
                int r = i / BV, c = i % BV;
                size_t off = (size_t)(kc + r) * FOUT + c * 8;
                *reinterpret_cast<uint4*>(&Bhs[r][c * 8]) =
                    *reinterpret_cast<const uint4*>(Bhi + off);
                *reinterpret_cast<uint4*>(&Bls[r][c * 8]) =
                    *reinterpret_cast<const uint4*>(Blo + off);
            }
        }
        __syncthreads();

#pragma unroll
        for (int kk = 0; kk < KC / 16; kk++) {
            uint32_t rah[4], ral[4];
            ldsm4(rah, &Ahi[arow][kk * 16 + acol8]);
            ldsm4(ral, &Alo[arow][kk * 16 + acol8]);
            const int brow = kk * 16 + (lane & 15);
#pragma unroll
            for (int np = 0; np < NF / 2; np++) {
                uint32_t rbh[4], rbl[4];
                ldsm4t(rbh, &Bhs[brow][np * 16 + acol8]);
                ldsm4t(rbl, &Bls[brow][np * 16 + acol8]);
                mma16816(acc[2 * np + 0], rah, rbh[0], rbh[1]);
                mma16816(acc[2 * np + 1], rah, rbh[2], rbh[3]);
                mma16816(acc[2 * np + 0], ral, rbh[0], rbh[1]);
                mma16816(acc[2 * np + 1], ral, rbh[2], rbh[3]);
                mma16816(acc[2 * np + 0], rah, rbl[0], rbl[1]);
                mma16816(acc[2 * np + 1], rah, rbl[2], rbl[3]);
            }
        }
    }

    const int r0 = row0 + wrow + (lane >> 2);
    const int r1 = r0 + 8;
    if constexpr (BN_EPI) {
#pragma unroll
        for (int nf = 0; nf < NF; nf++) {
            int col = nf * 8 + (lane & 3) * 2;
            float sc0 = s_sc[col], sc1 = s_sc[col + 1];
            float sb0 = s_shb[col], sb1 = s_shb[col + 1];
            if (r0 < N_NODES) {
                float2 o = make_float2(
                    fmaxf(fmaf(acc[nf][0], sc0, sb0), 0.0f),
                    fmaxf(fmaf(acc[nf][1], sc1, sb1), 0.0f));
                *reinterpret_cast<float2*>(OutF + (size_t)r0 * FOUT + col) = o;
            }
            if (r1 < N_NODES) {
                float2 o = make_float2(
                    fmaxf(fmaf(acc[nf][2], sc0, sb0), 0.0f),
                    fmaxf(fmaf(acc[nf][3], sc1, sb1), 0.0f));
                *reinterpret_cast<float2*>(OutF + (size_t)r1 * FOUT + col) = o;
            }
        }
    } else {
        const float d0 = (r0 < N_NODES) ? g_dinv[r0] : 0.0f;
        const float d1 = (r1 < N_NODES) ? g_dinv[r1] : 0.0f;
#pragma unroll
        for (int nf = 0; nf < NF; nf++) {
            int col = nf * 8 + (lane & 3) * 2;
            if (r0 < N_NODES)
                *reinterpret_cast<__half2*>(OutH + (size_t)r0 * FOUT + col) =
                    __floats2half2_rn(acc[nf][0] * d0, acc[nf][1] * d0);
            if (r1 < N_NODES)
                *reinterpret_cast<__half2*>(OutH + (size_t)r1 * FOUT + col) =
                    __floats2half2_rn(acc[nf][2] * d1, acc[nf][3] * d1);
        }
    }
}

// ---- fused CSR aggregation + dinv scale + BN + ReLU (+ pool) --------------
template<int FOUT, bool POOL>
__global__ void agg_kernel(const __half* __restrict__ xw,
                           const float* __restrict__ bias,
                           const float* __restrict__ bn_g,
                           const float* __restrict__ bn_b,
                           const float* __restrict__ bn_m,
                           const float* __restrict__ bn_v,
                           float* __restrict__ out,
                           const int* __restrict__ batch)
{
    constexpr int VEC = FOUT / 32;        // 4 (FOUT=128) or 2 (FOUT=64)
    __shared__ float s_sc [FOUT];
    __shared__ float s_shb[FOUT];

    const int tid  = threadIdx.x;
    const int lane = tid & 31;
    const int wid  = tid >> 5;

    if (tid < FOUT) {
        float sc = bn_g[tid] * rsqrtf(bn_v[tid] + BN_EPS);
        s_sc [tid] = sc;
        s_shb[tid] = sc * (bias[tid] - bn_m[tid]) + bn_b[tid];
    }
    __syncthreads();

    const int node = blockIdx.x * 8 + wid;
    if (node >= N_NODES) return;

    const int beg = node * CAP;
    const int end = beg + g_ecnt[node];

    float acc[VEC];
#pragma unroll
    for (int k = 0; k < VEC; k++) acc[k] = 0.0f;

    auto gather = [&](int s) {
        if constexpr (VEC == 4) {
            uint2 raw = *reinterpret_cast<const uint2*>(xw + (size_t)s * FOUT + lane * 4);
            float2 f0 = __half22float2(*reinterpret_cast<__half2*>(&raw.x));
            float2 f1 = __half22float2(*reinterpret_cast<__half2*>(&raw.y));
            acc[0] += f0.x; acc[1] += f0.y;
            acc[2] += f1.x; acc[3] += f1.y;
        } else {
            __half2 raw = *reinterpret_cast<const __half2*>(xw + (size_t)s * FOUT + lane * 2);
            float2 f0 = __half22float2(raw);
            acc[0] += f0.x; acc[1] += f0.y;
        }
    };

    int b = beg;
    const int nfull = (end - beg) & ~31;
    for (; b < beg + nfull; b += 32) {
        int pk = g_csr[b + lane];
#pragma unroll 8
        for (int j = 0; j < 32; j++) {
            int s = __shfl_sync(0xffffffffu, pk, j);
            gather(s);
        }
    }
    if (b < end) {
        int e = b + lane;
        int ssrc = (e < end) ? g_csr[e] : 0;
        int cnt = end - b;
        for (int j = 0; j < cnt; j++) {
            int s = __shfl_sync(0xffffffffu, ssrc, j);
            gather(s);
        }
    }
    gather(node);   // self loop

    const float di = g_dinv[node];
    float y[VEC];
#pragma unroll
    for (int k = 0; k < VEC; k++) {
        int col = lane * VEC + k;
        y[k] = fmaxf(fmaf(acc[k] * di, s_sc[col], s_shb[col]), 0.0f);
    }

    if constexpr (POOL) {
        int g = batch[node];
#pragma unroll
        for (int k = 0; k < VEC; k++)
            red_add_f32(&g_sums[(size_t)g * 64 + lane * VEC + k], y[k]);
        if (lane == 0) red_add_f32(&g_cnt[g], 1.0f);
    } else {
        if constexpr (VEC == 4) {
            reinterpret_cast<float4*>(out)[(size_t)node * 32 + lane] =
                make_float4(y[0], y[1], y[2], y[3]);
        } else {
            reinterpret_cast<float2*>(out)[(size_t)node * 32 + lane] =
                make_float2(y[0], y[1]);
        }
    }
}

// ---- MLP head: one block (128 thr) per graph ------------------------------
__global__ void head_kernel(const float* __restrict__ fw0, const float* __restrict__ fb0,
                            const float* __restrict__ fw1, const float* __restrict__ fb1,
                            const float* __restrict__ ow,  const float* __restrict__ ob,
                            float* __restrict__ out)
{
    __shared__ float pooled[64], h0[128], h1[64];
    const int g = blockIdx.x;
    const int t = threadIdx.x;

    float inv = 1.0f / fmaxf(g_cnt[g], 1.0f);
    if (t < 64) pooled[t] = g_sums[(size_t)g * 64 + t] * inv;
    __syncthreads();

    float a = fb0[t];
#pragma unroll
    for (int k = 0; k < 64; k++) a = fmaf(pooled[k], fw0[k * 128 + t], a);
    h0[t] = fmaxf(a, 0.0f);
    __syncthreads();

    if (t < 64) {
        float b = fb1[t];
#pragma unroll
        for (int k = 0; k < 128; k++) b = fmaf(h0[k], fw1[k * 64 + t], b);
        h1[t] = fmaxf(b, 0.0f);
    }
    __syncthreads();

    if (t < 2) {
        float o = ob[t];
#pragma unroll
        for (int k = 0; k < 64; k++) o = fmaf(h1[k], ow[k * 2 + t], o);
        out[(size_t)g * 2 + t] = o;
    }
}

// ---------------------------------------------------------------------------
extern "C" void kernel_launch(void* const* d_in, const int* in_sizes, int n_in,
                              void* d_out, int out_size)
{
    const float* x          = (const float*)d_in[0];
    const int*   edge_index = (const int*)  d_in[1];
    const int*   batch      = (const int*)  d_in[2];

    int p = 3;
    if (in_sizes[3] == 1) p = 4;   // num_graphs scalar, if materialized

    const float* W [3]; const float* B [3];
    const float* Gm[3]; const float* Be[3];
    const float* Mn[3]; const float* Vr[3];
    for (int l = 0; l < 3; l++) {
        W [l] = (const float*)d_in[p + 6 * l + 0];
        B [l] = (const float*)d_in[p + 6 * l + 1];
        Gm[l] = (const float*)d_in[p + 6 * l + 2];
        Be[l] = (const float*)d_in[p + 6 * l + 3];
        Mn[l] = (const float*)d_in[p + 6 * l + 4];
        Vr[l] = (const float*)d_in[p + 6 * l + 5];
    }
    const float* fw0 = (const float*)d_in[p + 18];
    const float* fb0 = (const float*)d_in[p + 19];
    const float* fw1 = (const float*)d_in[p + 20];
    const float* fb1 = (const float*)d_in[p + 21];
    const float* ow  = (const float*)d_in[p + 22];
    const float* ob  = (const float*)d_in[p + 23];
    float* out = (float*)d_out;

    const int* src = edge_index;
    const int* dst = edge_index + N_EDGES;

    __half *xw, *w0hi, *w0lo, *w1hi, *w1lo, *w2hi, *w2lo;
    float  *bufB, *tbuf;
    void *ecntp, *sumsp, *cntp;
    cudaGetSymbolAddress((void**)&xw,   g_xw);
    cudaGetSymbolAddress((void**)&bufB, g_bufB);
    cudaGetSymbolAddress((void**)&tbuf, g_t);
    cudaGetSymbolAddress((void**)&w0hi, g_w0hi);
    cudaGetSymbolAddress((void**)&w0lo, g_w0lo);
    cudaGetSymbolAddress((void**)&w1hi, g_w1hi);
    cudaGetSymbolAddress((void**)&w1lo, g_w1lo);
    cudaGetSymbolAddress((void**)&w2hi, g_w2hi);
    cudaGetSymbolAddress((void**)&w2lo, g_w2lo);
    cudaGetSymbolAddress(&ecntp, g_ecnt);
    cudaGetSymbolAddress(&sumsp, g_sums);
    cudaGetSymbolAddress(&cntp,  g_cnt);

    // zero counters
    cudaMemsetAsync(ecntp, 0, N_NODES * sizeof(int));
    cudaMemsetAsync(sumsp, 0, N_GRAPHS * 64 * sizeof(float));
    cudaMemsetAsync(cntp,  0, N_GRAPHS * sizeof(float));

    // single-pass bucketed CSR build (+ fused weight split; 128 tail blocks)
    fill_wsplit_kernel<<<2176, 256>>>(src, dst, W[0], W[1], W[2]);
    dinv_kernel<<<(N_NODES + 255) / 256, 256>>>(x);

    const int AGG_BLOCKS = (N_NODES + 7) / 8;       // 12500
    const int MMA_BLOCKS = (N_NODES + 127) / 128;   // 782

    // layer 0: agg0 -> t[N][64] ; h = relu(bn(t@W0 + b)) via split-HMMA
    agg0_kernel<<<AGG_BLOCKS, 256>>>();
    mma_gemm_kernel<64, 128, true><<<MMA_BLOCKS, 256>>>(
        tbuf, w0hi, w0lo, bufB, nullptr, B[0], Gm[0], Be[0], Mn[0], Vr[0]);

    // layer 1: xw = (h @ W1)*dinv -> h = agg+BN+ReLU
    mma_gemm_kernel<128, 128, false><<<MMA_BLOCKS, 256>>>(
        bufB, w1hi, w1lo, nullptr, xw, nullptr, nullptr, nullptr, nullptr, nullptr);
    agg_kernel<128, false><<<AGG_BLOCKS, 256>>>(xw, B[1], Gm[1], Be[1], Mn[1], Vr[1], bufB, nullptr);

    // layer 2: xw = (h @ W2)*dinv -> pool
    mma_gemm_kernel<128, 64, false><<<MMA_BLOCKS, 256>>>(
        bufB, w2hi, w2lo, nullptr, xw, nullptr, nullptr, nullptr, nullptr, nullptr);
    agg_kernel<64, true><<<AGG_BLOCKS, 256>>>(xw, B[2], Gm[2], Be[2], Mn[2], Vr[2], nullptr, batch);

    // head
    head_kernel<<<N_GRAPHS, 128>>>(fw0, fb0, fw1, fb1, ow, ob, out);
}

// round 16
// speedup vs baseline: 1.0150x; 1.0150x over previous
#include <cuda_runtime.h>
#include <cuda_fp16.h>
#include <math.h>
#include <stdint.h>

// ---------------------------------------------------------------------------
// MolecularGNN: 3x GCNConv(+BN+ReLU) -> global mean pool -> MLP head
// Bucketed single-pass CSR + 2-term split-fp16 HMMA GEMMs (A exact, W hi-only).
// ---------------------------------------------------------------------------

#define N_NODES  100000
#define N_EDGES  3200000
#define N_GRAPHS 4096
#define BN_EPS   1e-5f
#define CAP      128         // slots per node; deg ~ Poisson(32), P(>128) ~ 0

// ---- scratch (device globals; allocation-free rule) -----------------------
__device__ __align__(256) int    g_ecnt  [N_NODES];
__device__ __align__(256) float  g_dinv  [N_NODES];
__device__ __align__(256) int    g_csr   [N_NODES * CAP];
__device__ __align__(256) __half g_xs    [N_NODES * 36];   // x * dinv (fp16)
__device__ __align__(256) float  g_t     [N_NODES * 48];   // aggregated x, padded
__device__ __align__(256) __half g_xw    [N_NODES * 128];  // (h@W)*dinv (fp16)
__device__ __align__(256) float  g_bufB  [N_NODES * 128];  // h (fp32)
__device__ __align__(256) __half g_w0h   [48 * 128];
__device__ __align__(256) __half g_w1h   [128 * 128];
__device__ __align__(256) __half g_w2h   [128 * 64];
__device__ __align__(256) float  g_sums  [N_GRAPHS * 64];
__device__ __align__(256) float  g_cnt   [N_GRAPHS];

__device__ __forceinline__ void red_add_f32(float* p, float v) {
    asm volatile("red.global.add.f32 [%0], %1;" :: "l"(p), "f"(v) : "memory");
}

// ---- mma helpers ----------------------------------------------------------
__device__ __forceinline__ void ldsm4(uint32_t* r, const void* p) {
    uint32_t addr = (uint32_t)__cvta_generic_to_shared(p);
    asm volatile("ldmatrix.sync.aligned.m8n8.x4.shared.b16 {%0,%1,%2,%3}, [%4];"
        : "=r"(r[0]), "=r"(r[1]), "=r"(r[2]), "=r"(r[3]) : "r"(addr));
}
__device__ __forceinline__ void ldsm4t(uint32_t* r, const void* p) {
    uint32_t addr = (uint32_t)__cvta_generic_to_shared(p);
    asm volatile("ldmatrix.sync.aligned.m8n8.x4.trans.shared.b16 {%0,%1,%2,%3}, [%4];"
        : "=r"(r[0]), "=r"(r[1]), "=r"(r[2]), "=r"(r[3]) : "r"(addr));
}
__device__ __forceinline__ void mma16816(float* c, const uint32_t* a,
                                         uint32_t b0, uint32_t b1) {
    asm volatile("mma.sync.aligned.m16n8k16.row.col.f32.f16.f16.f32 "
        "{%0,%1,%2,%3}, {%4,%5,%6,%7}, {%8,%9}, {%0,%1,%2,%3};"
        : "+f"(c[0]), "+f"(c[1]), "+f"(c[2]), "+f"(c[3])
        : "r"(a[0]), "r"(a[1]), "r"(a[2]), "r"(a[3]), "r"(b0), "r"(b1));
}
__device__ __forceinline__ void split2(float a, float b, uint32_t& hi, uint32_t& lo) {
    __half h0 = __float2half_rn(a), h1 = __float2half_rn(b);
    __half l0 = __float2half_rn(a - __half2float(h0));
    __half l1 = __float2half_rn(b - __half2float(h1));
    __half2 ph = __halves2half2(h0, h1), pl = __halves2half2(l0, l1);
    hi = *reinterpret_cast<uint32_t*>(&ph);
    lo = *reinterpret_cast<uint32_t*>(&pl);
}

// ---- single-pass bucketed CSR fill (x4 ILP) + weight fp16 convert (tail) --
__global__ void fill_wsplit_kernel(const int* __restrict__ src,
                                   const int* __restrict__ dst,
                                   const float* __restrict__ w0,
                                   const float* __restrict__ w1,
                                   const float* __restrict__ w2)
{
    if (blockIdx.x < 2048) {
        const int t = blockIdx.x * 256 + threadIdx.x;
        const int stride4 = 2048 * 256 * 4;
        for (int e4 = t * 4; e4 < N_EDGES; e4 += stride4) {   // N_EDGES % 4 == 0
            int4 d4 = *reinterpret_cast<const int4*>(dst + e4);
            int4 s4 = *reinterpret_cast<const int4*>(src + e4);
            int p0 = atomicAdd(&g_ecnt[d4.x], 1);
            int p1 = atomicAdd(&g_ecnt[d4.y], 1);
            int p2 = atomicAdd(&g_ecnt[d4.z], 1);
            int p3 = atomicAdd(&g_ecnt[d4.w], 1);
            if (p0 < CAP) g_csr[(size_t)d4.x * CAP + p0] = s4.x;
            if (p1 < CAP) g_csr[(size_t)d4.y * CAP + p1] = s4.y;
            if (p2 < CAP) g_csr[(size_t)d4.z * CAP + p2] = s4.z;
            if (p3 < CAP) g_csr[(size_t)d4.w * CAP + p3] = s4.w;
        }
    } else {
        int i = (blockIdx.x - 2048) * 256 + threadIdx.x;   // 0..30719
        if (i < 6144) {            // W0 padded to 48x128
            int row = i >> 7;
            float v = (row < 36) ? w0[i] : 0.0f;
            g_w0h[i] = __float2half_rn(v);
        } else if (i < 6144 + 16384) {
            int j = i - 6144;
            g_w1h[j] = __float2half_rn(w1[j]);
        } else {
            int j = i - 6144 - 16384;   // < 8192
            g_w2h[j] = __float2half_rn(w2[j]);
        }
    }
}

// ---- dinv + x -> fp16*dinv ------------------------------------------------
__global__ void dinv_kernel(const float* __restrict__ x) {
    int i = blockIdx.x * blockDim.x + threadIdx.x;
    if (i < N_NODES) {
        float di = rsqrtf((float)g_ecnt[i] + 1.0f);
        g_dinv[i] = di;
        const float2* xr = reinterpret_cast<const float2*>(x + (size_t)i * 36);
        __half2* xo = reinterpret_cast<__half2*>(g_xs + (size_t)i * 36);
#pragma unroll
        for (int j = 0; j < 18; j++) {
            float2 v = xr[j];
            xo[j] = __floats2half2_rn(v.x * di, v.y * di);
        }
    }
}

// ---- layer-0 aggregation over 36-wide fp16 rows -> t[N][48] (padded) ------
__global__ void agg0_kernel() {
    const int tid  = threadIdx.x;
    const int lane = tid & 31;
    const int wid  = tid >> 5;
    const int node = blockIdx.x * 8 + wid;
    if (node >= N_NODES) return;

    const int beg = node * CAP;
    const int end = beg + g_ecnt[node];

    float a0 = 0.0f, a1 = 0.0f;
    const bool act = (lane < 18);

    auto gather = [&](int s) {
        if (act) {
            __half2 v = *reinterpret_cast<const __half2*>(g_xs + (size_t)s * 36 + lane * 2);
            float2 f = __half22float2(v);
            a0 += f.x; a1 += f.y;
        }
    };

    int b = beg;
    const int nfull = (end - beg) & ~31;
    for (; b < beg + nfull; b += 32) {
        int pk = g_csr[b + lane];
#pragma unroll 8
        for (int j = 0; j < 32; j++) {
            int s = __shfl_sync(0xffffffffu, pk, j);
            gather(s);
        }
    }
    if (b < end) {
        int e = b + lane;
        int ssrc = (e < end) ? g_csr[e] : 0;
        int cnt = end - b;
        for (int j = 0; j < cnt; j++) {
            int s = __shfl_sync(0xffffffffu, ssrc, j);
            gather(s);
        }
    }
    gather(node);   // self loop

    if (lane < 24) {
        float di = g_dinv[node];
        float2 o = (lane < 18) ? make_float2(a0 * di, a1 * di) : make_float2(0.f, 0.f);
        *reinterpret_cast<float2*>(g_t + (size_t)node * 48 + lane * 2) = o;
    }
}

// ---- 2-term split-fp16 tensor-core GEMM (A exact, W hi-only) --------------
// 256 threads (8 warps) x 128-row tile; KC=16.
// C = (Ahi + Alo) @ Whi ; A split during staging, W pre-converted fp16.
template<int FIN, int FOUT, bool BN_EPI>
__global__ __launch_bounds__(256) void mma_gemm_kernel(
    const float* __restrict__ A,      // [N, FIN] fp32
    const __half* __restrict__ Bh,    // [FIN, FOUT] fp16
    float* __restrict__ OutF,
    __half* __restrict__ OutH,
    const float* __restrict__ bias,
    const float* __restrict__ bn_g, const float* __restrict__ bn_b,
    const float* __restrict__ bn_m, const float* __restrict__ bn_v)
{
    constexpr int KC = 16;
    constexpr int NF = FOUT / 8;
    __shared__ __half Ahi[128][KC + 8];
    __shared__ __half Alo[128][KC + 8];
    __shared__ __half Bhs[KC][FOUT + 8];
    __shared__ float s_sc [FOUT];
    __shared__ float s_shb[FOUT];

    const int tid  = threadIdx.x;
    const int lane = tid & 31;
    const int warp = tid >> 5;
    const int row0 = blockIdx.x * 128;

    if constexpr (BN_EPI) {
        if (tid < FOUT) {
            float sc = bn_g[tid] * rsqrtf(bn_v[tid] + BN_EPS);
            s_sc [tid] = sc;
            s_shb[tid] = sc * (bias[tid] - bn_m[tid]) + bn_b[tid];
        }
    }

    float acc[NF][4];
#pragma unroll
    for (int nf = 0; nf < NF; nf++)
#pragma unroll
        for (int j = 0; j < 4; j++) acc[nf][j] = 0.0f;

    const int wrow  = warp * 16;
    const int arow  = wrow + (lane & 15);
    const int acol8 = (lane >> 4) * 8;

    for (int kc = 0; kc < FIN; kc += KC) {
        __syncthreads();
        // stage A chunk (128 x 16 fp32 -> hi/lo)
        {
            constexpr int C4 = KC / 4;   // 4
            for (int i = tid; i < 128 * C4; i += 256) {
                int r = i / C4, c4 = i % C4;
                float4 v = make_float4(0.f, 0.f, 0.f, 0.f);
                if (row0 + r < N_NODES)
                    v = *reinterpret_cast<const float4*>(
                        A + (size_t)(row0 + r) * FIN + kc + c4 * 4);
                uint32_t h0, l0, h1, l1;
                split2(v.x, v.y, h0, l0);
                split2(v.z, v.w, h1, l1);
                uint2 uh = make_uint2(h0, h1), ul = make_uint2(l0, l1);
                *reinterpret_cast<uint2*>(&Ahi[r][c4 * 4]) = uh;
                *reinterpret_cast<uint2*>(&Alo[r][c4 * 4]) = ul;
            }
        }
        // stage B chunk (16 x FOUT, hi only)
        {
            constexpr int BV = FOUT / 8;
            for (int i = tid; i < KC * BV; i += 256) {
                int r = i / BV, c = i % BV;
                size_t off = (size_t)(kc + r) * FOUT + c * 8;
                *reinterpret_cast<uint4*>(&Bhs[r][c * 8]) =
                    *reinterpret_cast<const uint4*>(Bh + off);
            }
        }
        __syncthreads();

        uint32_t rah[4], ral[4];
        ldsm4(rah, &Ahi[arow][acol8]);
        ldsm4(ral, &Alo[arow][acol8]);
        const int brow = (lane & 15);
#pragma unroll
        for (int np = 0; np < NF / 2; np++) {
            uint32_t rbh[4];
            ldsm4t(rbh, &Bhs[brow][np * 16 + acol8]);
            mma16816(acc[2 * np + 0], rah, rbh[0], rbh[1]);
            mma16816(acc[2 * np + 1], rah, rbh[2], rbh[3]);
            mma16816(acc[2 * np + 0], ral, rbh[0], rbh[1]);
            mma16816(acc[2 * np + 1], ral, rbh[2], rbh[3]);
        }
    }

    const int r0 = row0 + wrow + (lane >> 2);
    const int r1 = r0 + 8;
    if constexpr (BN_EPI) {
#pragma unroll
        for (int nf = 0; nf < NF; nf++) {
            int col = nf * 8 + (lane & 3) * 2;
            float sc0 = s_sc[col], sc1 = s_sc[col + 1];
            float sb0 = s_shb[col], sb1 = s_shb[col + 1];
            if (r0 < N_NODES) {
                float2 o = make_float2(
                    fmaxf(fmaf(acc[nf][0], sc0, sb0), 0.0f),
                    fmaxf(fmaf(acc[nf][1], sc1, sb1), 0.0f));
                *reinterpret_cast<float2*>(OutF + (size_t)r0 * FOUT + col) = o;
            }
            if (r1 < N_NODES) {
                float2 o = make_float2(
                    fmaxf(fmaf(acc[nf][2], sc0, sb0), 0.0f),
                    fmaxf(fmaf(acc[nf][3], sc1, sb1), 0.0f));
                *reinterpret_cast<float2*>(OutF + (size_t)r1 * FOUT + col) = o;
            }
        }
    } else {
        const float d0 = (r0 < N_NODES) ? g_dinv[r0] : 0.0f;
        const float d1 = (r1 < N_NODES) ? g_dinv[r1] : 0.0f;
#pragma unroll
        for (int nf = 0; nf < NF; nf++) {
            int col = nf * 8 + (lane & 3) * 2;
            if (r0 < N_NODES)
                *reinterpret_cast<__half2*>(OutH + (size_t)r0 * FOUT + col) =
                    __floats2half2_rn(acc[nf][0] * d0, acc[nf][1] * d0);
            if (r1 < N_NODES)
                *reinterpret_cast<__half2*>(OutH + (size_t)r1 * FOUT + col) =
                    __floats2half2_rn(acc[nf][2] * d1, acc[nf][3] * d1);
        }
    }
}

// ---- fused CSR aggregation + dinv scale + BN + ReLU (+ pool) --------------
template<int FOUT, bool POOL>
__global__ void agg_kernel(const __half* __restrict__ xw,
                           const float* __restrict__ bias,
                           const float* __restrict__ bn_g,
                           const float* __restrict__ bn_b,
                           const float* __restrict__ bn_m,
                           const float* __restrict__ bn_v,
                           float* __restrict__ out,
                           const int* __restrict__ batch)
{
    constexpr int VEC = FOUT / 32;        // 4 (FOUT=128) or 2 (FOUT=64)
    __shared__ float s_sc [FOUT];
    __shared__ float s_shb[FOUT];

    const int tid  = threadIdx.x;
    const int lane = tid & 31;
    const int wid  = tid >> 5;

    if (tid < FOUT) {
        float sc = bn_g[tid] * rsqrtf(bn_v[tid] + BN_EPS);
        s_sc [tid] = sc;
        s_shb[tid] = sc * (bias[tid] - bn_m[tid]) + bn_b[tid];
    }
    __syncthreads();

    const int node = blockIdx.x * 8 + wid;
    if (node >= N_NODES) return;

    const int beg = node * CAP;
    const int end = beg + g_ecnt[node];

    float acc[VEC];
#pragma unroll
    for (int k = 0; k < VEC; k++) acc[k] = 0.0f;

    auto gather = [&](int s) {
        if constexpr (VEC == 4) {
            uint2 raw = *reinterpret_cast<const uint2*>(xw + (size_t)s * FOUT + lane * 4);
            float2 f0 = __half22float2(*reinterpret_cast<__half2*>(&raw.x));
            float2 f1 = __half22float2(*reinterpret_cast<__half2*>(&raw.y));
            acc[0] += f0.x; acc[1] += f0.y;
            acc[2] += f1.x; acc[3] += f1.y;
        } else {
            __half2 raw = *reinterpret_cast<const __half2*>(xw + (size_t)s * FOUT + lane * 2);
            float2 f0 = __half22float2(raw);
            acc[0] += f0.x; acc[1] += f0.y;
        }
    };

    int b = beg;
    const int nfull = (end - beg) & ~31;
    for (; b < beg + nfull; b += 32) {
        int pk = g_csr[b + lane];
#pragma unroll 8
        for (int j = 0; j < 32; j++) {
            int s = __shfl_sync(0xffffffffu, pk, j);
            gather(s);
        }
    }
    if (b < end) {
        int e = b + lane;
        int ssrc = (e < end) ? g_csr[e] : 0;
        int cnt = end - b;
        for (int j = 0; j < cnt; j++) {
            int s = __shfl_sync(0xffffffffu, ssrc, j);
            gather(s);
        }
    }
    gather(node);   // self loop

    const float di = g_dinv[node];
    float y[VEC];
#pragma unroll
    for (int k = 0; k < VEC; k++) {
        int col = lane * VEC + k;
        y[k] = fmaxf(fmaf(acc[k] * di, s_sc[col], s_shb[col]), 0.0f);
    }

    if constexpr (POOL) {
        int g = batch[node];
#pragma unroll
        for (int k = 0; k < VEC; k++)
            red_add_f32(&g_sums[(size_t)g * 64 + lane * VEC + k], y[k]);
        if (lane == 0) red_add_f32(&g_cnt[g], 1.0f);
    } else {
        if constexpr (VEC == 4) {
            reinterpret_cast<float4*>(out)[(size_t)node * 32 + lane] =
                make_float4(y[0], y[1], y[2], y[3]);
        } else {
            reinterpret_cast<float2*>(out)[(size_t)node * 32 + lane] =
                make_float2(y[0], y[1]);
        }
    }
}

// ---- MLP head: one block (128 thr) per graph ------------------------------
__global__ void head_kernel(const float* __restrict__ fw0, const float* __restrict__ fb0,
                            const float* __restrict__ fw1, const float* __restrict__ fb1,
                            const float* __restrict__ ow,  const float* __restrict__ ob,
                            float* __restrict__ out)
{
    __shared__ float pooled[64], h0[128], h1[64];
    const int g = blockIdx.x;
    const int t = threadIdx.x;

    float inv = 1.0f / fmaxf(g_cnt[g], 1.0f);
    if (t < 64) pooled[t] = g_sums[(size_t)g * 64 + t] * inv;
    __syncthreads();

    float a = fb0[t];
#pragma unroll
    for (int k = 0; k < 64; k++) a = fmaf(pooled[k], fw0[k * 128 + t], a);
    h0[t] = fmaxf(a, 0.0f);
    __syncthreads();

    if (t < 64) {
        float b = fb1[t];
#pragma unroll
        for (int k = 0; k < 128; k++) b = fmaf(h0[k], fw1[k * 64 + t], b);
        h1[t] = fmaxf(b, 0.0f);
    }
    __syncthreads();

    if (t < 2) {
        float o = ob[t];
#pragma unroll
        for (int k = 0; k < 64; k++) o = fmaf(h1[k], ow[k * 2 + t], o);
        out[(size_t)g * 2 + t] = o;
    }
}

// ---------------------------------------------------------------------------
extern "C" void kernel_launch(void* const* d_in, const int* in_sizes, int n_in,
                              void* d_out, int out_size)
{
    const float* x          = (const float*)d_in[0];
    const int*   edge_index = (const int*)  d_in[1];
    const int*   batch      = (const int*)  d_in[2];

    int p = 3;
    if (in_sizes[3] == 1) p = 4;   // num_graphs scalar, if materialized

    const float* W [3]; const float* B [3];
    const float* Gm[3]; const float* Be[3];
    const float* Mn[3]; const float* Vr[3];
    for (int l = 0; l < 3; l++) {
        W [l] = (const float*)d_in[p + 6 * l + 0];
        B [l] = (const float*)d_in[p + 6 * l + 1];
        Gm[l] = (const float*)d_in[p + 6 * l + 2];
        Be[l] = (const float*)d_in[p + 6 * l + 3];
        Mn[l] = (const float*)d_in[p + 6 * l + 4];
        Vr[l] = (const float*)d_in[p + 6 * l + 5];
    }
    const float* fw0 = (const float*)d_in[p + 18];
    const float* fb0 = (const float*)d_in[p + 19];
    const float* fw1 = (const float*)d_in[p + 20];
    const float* fb1 = (const float*)d_in[p + 21];
    const float* ow  = (const float*)d_in[p + 22];
    const float* ob  = (const float*)d_in[p + 23];
    float* out = (float*)d_out;

    const int* src = edge_index;
    const int* dst = edge_index + N_EDGES;

    __half *xw, *w0h, *w1h, *w2h;
    float  *bufB, *tbuf;
    void *ecntp, *sumsp, *cntp;
    cudaGetSymbolAddress((void**)&xw,   g_xw);
    cudaGetSymbolAddress((void**)&bufB, g_bufB);
    cudaGetSymbolAddress((void**)&tbuf, g_t);
    cudaGetSymbolAddress((void**)&w0h,  g_w0h);
    cudaGetSymbolAddress((void**)&w1h,  g_w1h);
    cudaGetSymbolAddress((void**)&w2h,  g_w2h);
    cudaGetSymbolAddress(&ecntp, g_ecnt);
    cudaGetSymbolAddress(&sumsp, g_sums);
    cudaGetSymbolAddress(&cntp,  g_cnt);

    // zero counters
    cudaMemsetAsync(ecntp, 0, N_NODES * sizeof(int));
    cudaMemsetAsync(sumsp, 0, N_GRAPHS * 64 * sizeof(float));
    cudaMemsetAsync(cntp,  0, N_GRAPHS * sizeof(float));

    // single-pass bucketed CSR build (+ fused weight fp16 convert)
    fill_wsplit_kernel<<<2168, 256>>>(src, dst, W[0], W[1], W[2]);
    dinv_kernel<<<(N_NODES + 255) / 256, 256>>>(x);

    const int AGG_BLOCKS = (N_NODES + 7) / 8;       // 12500
    const int MMA_BLOCKS = (N_NODES + 127) / 128;   // 782

    // layer 0: agg0 -> t[N][48] ; h = relu(bn(t@W0 + b)) via 2-term HMMA
    agg0_kernel<<<AGG_BLOCKS, 256>>>();
    mma_gemm_kernel<48, 128, true><<<MMA_BLOCKS, 256>>>(
        tbuf, w0h, bufB, nullptr, B[0], Gm[0], Be[0], Mn[0], Vr[0]);

    // layer 1: xw = (h @ W1)*dinv -> h = agg+BN+ReLU
    mma_gemm_kernel<128, 128, false><<<MMA_BLOCKS, 256>>>(
        bufB, w1h, nullptr, xw, nullptr, nullptr, nullptr, nullptr, nullptr);
    agg_kernel<128, false><<<AGG_BLOCKS, 256>>>(xw, B[1], Gm[1], Be[1], Mn[1], Vr[1], bufB, nullptr);

    // layer 2: xw = (h @ W2)*dinv -> pool
    mma_gemm_kernel<128, 64, false><<<MMA_BLOCKS, 256>>>(
        bufB, w2h, nullptr, xw, nullptr, nullptr, nullptr, nullptr, nullptr);
    agg_kernel<64, true><<<AGG_BLOCKS, 256>>>(xw, B[2], Gm[2], Be[2], Mn[2], Vr[2], nullptr, batch);

    // head
    head_kernel<<<N_GRAPHS, 128>>>(fw0, fb0, fw1, fb1, ow, ob, out);
}

// round 17
// speedup vs baseline: 1.0981x; 1.0819x over previous
#include <cuda_runtime.h>
#include <cuda_fp16.h>
#include <math.h>
#include <stdint.h>

// ---------------------------------------------------------------------------
// MolecularGNN: 3x GCNConv(+BN+ReLU) -> global mean pool -> MLP head
// Bucketed single-pass CSR + fp16 features + W-exact (hi/lo) 2-term HMMA.
// A-side fp16 errors are node-iid (average out in pooling); W kept exact.
// ---------------------------------------------------------------------------

#define N_NODES  100000
#define N_EDGES  3200000
#define N_GRAPHS 4096
#define BN_EPS   1e-5f
#define CAP      128         // slots per node; deg ~ Poisson(32), P(>128) ~ 0

// ---- scratch (device globals; allocation-free rule) -----------------------
__device__ __align__(256) int    g_ecnt  [N_NODES];
__device__ __align__(256) float  g_dinv  [N_NODES];
__device__ __align__(256) int    g_csr   [N_NODES * CAP];
__device__ __align__(256) __half g_xs    [N_NODES * 36];   // x * dinv (fp16)
__device__ __align__(256) __half g_t     [N_NODES * 48];   // aggregated x (fp16, padded)
__device__ __align__(256) __half g_xw    [N_NODES * 128];  // (h@W)*dinv (fp16)
__device__ __align__(256) __half g_h16   [N_NODES * 128];  // h (fp16)
__device__ __align__(256) __half g_w0hi  [48 * 128];
__device__ __align__(256) __half g_w0lo  [48 * 128];
__device__ __align__(256) __half g_w1hi  [128 * 128];
__device__ __align__(256) __half g_w1lo  [128 * 128];
__device__ __align__(256) __half g_w2hi  [128 * 64];
__device__ __align__(256) __half g_w2lo  [128 * 64];
__device__ __align__(256) float  g_sums  [N_GRAPHS * 64];
__device__ __align__(256) float  g_cnt   [N_GRAPHS];

__device__ __forceinline__ void red_add_f32(float* p, float v) {
    asm volatile("red.global.add.f32 [%0], %1;" :: "l"(p), "f"(v) : "memory");
}

// ---- mma helpers ----------------------------------------------------------
__device__ __forceinline__ void ldsm4(uint32_t* r, const void* p) {
    uint32_t addr = (uint32_t)__cvta_generic_to_shared(p);
    asm volatile("ldmatrix.sync.aligned.m8n8.x4.shared.b16 {%0,%1,%2,%3}, [%4];"
        : "=r"(r[0]), "=r"(r[1]), "=r"(r[2]), "=r"(r[3]) : "r"(addr));
}
__device__ __forceinline__ void ldsm4t(uint32_t* r, const void* p) {
    uint32_t addr = (uint32_t)__cvta_generic_to_shared(p);
    asm volatile("ldmatrix.sync.aligned.m8n8.x4.trans.shared.b16 {%0,%1,%2,%3}, [%4];"
        : "=r"(r[0]), "=r"(r[1]), "=r"(r[2]), "=r"(r[3]) : "r"(addr));
}
__device__ __forceinline__ void mma16816(float* c, const uint32_t* a,
                                         uint32_t b0, uint32_t b1) {
    asm volatile("mma.sync.aligned.m16n8k16.row.col.f32.f16.f16.f32 "
        "{%0,%1,%2,%3}, {%4,%5,%6,%7}, {%8,%9}, {%0,%1,%2,%3};"
        : "+f"(c[0]), "+f"(c[1]), "+f"(c[2]), "+f"(c[3])
        : "r"(a[0]), "r"(a[1]), "r"(a[2]), "r"(a[3]), "r"(b0), "r"(b1));
}

// ---- single-pass bucketed CSR fill (x4 ILP) + W hi/lo split (tail) --------
__global__ void fill_wsplit_kernel(const int* __restrict__ src,
                                   const int* __restrict__ dst,
                                   const float* __restrict__ w0,
                                   const float* __restrict__ w1,
                                   const float* __restrict__ w2)
{
    if (blockIdx.x < 2048) {
        const int t = blockIdx.x * 256 + threadIdx.x;
        const int stride4 = 2048 * 256 * 4;
        for (int e4 = t * 4; e4 < N_EDGES; e4 += stride4) {   // N_EDGES % 4 == 0
            int4 d4 = *reinterpret_cast<const int4*>(dst + e4);
            int4 s4 = *reinterpret_cast<const int4*>(src + e4);
            int p0 = atomicAdd(&g_ecnt[d4.x], 1);
            int p1 = atomicAdd(&g_ecnt[d4.y], 1);
            int p2 = atomicAdd(&g_ecnt[d4.z], 1);
            int p3 = atomicAdd(&g_ecnt[d4.w], 1);
            if (p0 < CAP) g_csr[(size_t)d4.x * CAP + p0] = s4.x;
            if (p1 < CAP) g_csr[(size_t)d4.y * CAP + p1] = s4.y;
            if (p2 < CAP) g_csr[(size_t)d4.z * CAP + p2] = s4.z;
            if (p3 < CAP) g_csr[(size_t)d4.w * CAP + p3] = s4.w;
        }
    } else {
        int i = (blockIdx.x - 2048) * 256 + threadIdx.x;   // 0..30719
        if (i < 6144) {            // W0 padded to 48x128
            int row = i >> 7;
            float v = (row < 36) ? w0[i] : 0.0f;
            __half h = __float2half_rn(v);
            g_w0hi[i] = h;
            g_w0lo[i] = __float2half_rn(v - __half2float(h));
        } else if (i < 6144 + 16384) {
            int j = i - 6144;
            float v = w1[j];
            __half h = __float2half_rn(v);
            g_w1hi[j] = h;
            g_w1lo[j] = __float2half_rn(v - __half2float(h));
        } else {
            int j = i - 6144 - 16384;   // < 8192
            float v = w2[j];
            __half h = __float2half_rn(v);
            g_w2hi[j] = h;
            g_w2lo[j] = __float2half_rn(v - __half2float(h));
        }
    }
}

// ---- dinv + x -> fp16*dinv ------------------------------------------------
__global__ void dinv_kernel(const float* __restrict__ x) {
    int i = blockIdx.x * blockDim.x + threadIdx.x;
    if (i < N_NODES) {
        float di = rsqrtf((float)g_ecnt[i] + 1.0f);
        g_dinv[i] = di;
        const float2* xr = reinterpret_cast<const float2*>(x + (size_t)i * 36);
        __half2* xo = reinterpret_cast<__half2*>(g_xs + (size_t)i * 36);
#pragma unroll
        for (int j = 0; j < 18; j++) {
            float2 v = xr[j];
            xo[j] = __floats2half2_rn(v.x * di, v.y * di);
        }
    }
}

// ---- layer-0 aggregation over 36-wide fp16 rows -> t[N][48] fp16 ----------
__global__ void agg0_kernel() {
    const int tid  = threadIdx.x;
    const int lane = tid & 31;
    const int wid  = tid >> 5;
    const int node = blockIdx.x * 8 + wid;
    if (node >= N_NODES) return;

    const int beg = node * CAP;
    const int end = beg + g_ecnt[node];

    float a0 = 0.0f, a1 = 0.0f;
    const bool act = (lane < 18);

    auto gather = [&](int s) {
        if (act) {
            __half2 v = *reinterpret_cast<const __half2*>(g_xs + (size_t)s * 36 + lane * 2);
            float2 f = __half22float2(v);
            a0 += f.x; a1 += f.y;
        }
    };

    int b = beg;
    const int nfull = (end - beg) & ~31;
    for (; b < beg + nfull; b += 32) {
        int pk = g_csr[b + lane];
#pragma unroll 8
        for (int j = 0; j < 32; j++) {
            int s = __shfl_sync(0xffffffffu, pk, j);
            gather(s);
        }
    }
    if (b < end) {
        int e = b + lane;
        int ssrc = (e < end) ? g_csr[e] : 0;
        int cnt = end - b;
        for (int j = 0; j < cnt; j++) {
            int s = __shfl_sync(0xffffffffu, ssrc, j);
            gather(s);
        }
    }
    gather(node);   // self loop

    if (lane < 24) {
        float di = g_dinv[node];
        __half2 o = (lane < 18) ? __floats2half2_rn(a0 * di, a1 * di)
                                : __floats2half2_rn(0.f, 0.f);
        *reinterpret_cast<__half2*>(g_t + (size_t)node * 48 + lane * 2) = o;
    }
}

// ---- fp16-A, W-exact 2-term HMMA GEMM: C = A@(Whi+Wlo) --------------------
// 256 threads (8 warps) x 128-row tile; KC=16. A fp16 [N,FIN] staged verbatim.
// BN_EPI=true : h16 = relu(sc*C + shb)      (fp16 out)
// BN_EPI=false: xw  = C * dinv[row]         (fp16 out)
template<int FIN, int FOUT, bool BN_EPI>
__global__ __launch_bounds__(256) void mma_gemm_kernel(
    const __half* __restrict__ A,     // [N, FIN] fp16
    const __half* __restrict__ Bhi,   // [FIN, FOUT]
    const __half* __restrict__ Blo,
    __half* __restrict__ Out,
    const float* __restrict__ bias,
    const float* __restrict__ bn_g, const float* __restrict__ bn_b,
    const float* __restrict__ bn_m, const float* __restrict__ bn_v)
{
    constexpr int KC = 16;
    constexpr int NF = FOUT / 8;
    __shared__ __half Ahs[128][KC + 8];
    __shared__ __half Bhs[KC][FOUT + 8];
    __shared__ __half Bls[KC][FOUT + 8];
    __shared__ float s_sc [FOUT];
    __shared__ float s_shb[FOUT];

    const int tid  = threadIdx.x;
    const int lane = tid & 31;
    const int warp = tid >> 5;
    const int row0 = blockIdx.x * 128;

    if constexpr (BN_EPI) {
        if (tid < FOUT) {
            float sc = bn_g[tid] * rsqrtf(bn_v[tid] + BN_EPS);
            s_sc [tid] = sc;
            s_shb[tid] = sc * (bias[tid] - bn_m[tid]) + bn_b[tid];
        }
    }

    float acc[NF][4];
#pragma unroll
    for (int nf = 0; nf < NF; nf++)
#pragma unroll
        for (int j = 0; j < 4; j++) acc[nf][j] = 0.0f;

    const int wrow  = warp * 16;
    const int arow  = wrow + (lane & 15);
    const int acol8 = (lane >> 4) * 8;

    for (int kc = 0; kc < FIN; kc += KC) {
        __syncthreads();
        // stage A chunk (128 x 16 fp16) — verbatim uint4 copies
        {
            // 2 uint4 segments per row -> 256 segments, 1 per thread
            int r = tid >> 1, seg = tid & 1;
            uint4 v = make_uint4(0u, 0u, 0u, 0u);
            if (row0 + r < N_NODES)
                v = *reinterpret_cast<const uint4*>(
                    A + (size_t)(row0 + r) * FIN + kc + seg * 8);
            *reinterpret_cast<uint4*>(&Ahs[r][seg * 8]) = v;
        }
        // stage B chunk (16 x FOUT, hi and lo)
        {
            constexpr int BV = FOUT / 8;
            for (int i = tid; i < KC * BV; i += 256) {
                int r = i / BV, c = i % BV;
                size_t off = (size_t)(kc + r) * FOUT + c * 8;
                *reinterpret_cast<uint4*>(&Bhs[r][c * 8]) =
                    *reinterpret_cast<const uint4*>(Bhi + off);
                *reinterpret_cast<uint4*>(&Bls[r][c * 8]) =
                    *reinterpret_cast<const uint4*>(Blo + off);
            }
        }
        __syncthreads();

        uint32_t ra[4];
        ldsm4(ra, &Ahs[arow][acol8]);
        const int brow = (lane & 15);
#pragma unroll
        for (int np = 0; np < NF / 2; np++) {
            uint32_t rbh[4], rbl[4];
            ldsm4t(rbh, &Bhs[brow][np * 16 + acol8]);
            ldsm4t(rbl, &Bls[brow][np * 16 + acol8]);
            mma16816(acc[2 * np + 0], ra, rbh[0], rbh[1]);
            mma16816(acc[2 * np + 1], ra, rbh[2], rbh[3]);
            mma16816(acc[2 * np + 0], ra, rbl[0], rbl[1]);
            mma16816(acc[2 * np + 1], ra, rbl[2], rbl[3]);
        }
    }

    const int r0 = row0 + wrow + (lane >> 2);
    const int r1 = r0 + 8;
    if constexpr (BN_EPI) {
#pragma unroll
        for (int nf = 0; nf < NF; nf++) {
            int col = nf * 8 + (lane & 3) * 2;
            float sc0 = s_sc[col], sc1 = s_sc[col + 1];
            float sb0 = s_shb[col], sb1 = s_shb[col + 1];
            if (r0 < N_NODES)
                *reinterpret_cast<__half2*>(Out + (size_t)r0 * FOUT + col) =
                    __floats2half2_rn(fmaxf(fmaf(acc[nf][0], sc0, sb0), 0.0f),
                                      fmaxf(fmaf(acc[nf][1], sc1, sb1), 0.0f));
            if (r1 < N_NODES)
                *reinterpret_cast<__half2*>(Out + (size_t)r1 * FOUT + col) =
                    __floats2half2_rn(fmaxf(fmaf(acc[nf][2], sc0, sb0), 0.0f),
                                      fmaxf(fmaf(acc[nf][3], sc1, sb1), 0.0f));
        }
    } else {
        const float d0 = (r0 < N_NODES) ? g_dinv[r0] : 0.0f;
        const float d1 = (r1 < N_NODES) ? g_dinv[r1] : 0.0f;
#pragma unroll
        for (int nf = 0; nf < NF; nf++) {
            int col = nf * 8 + (lane & 3) * 2;
            if (r0 < N_NODES)
                *reinterpret_cast<__half2*>(Out + (size_t)r0 * FOUT + col) =
                    __floats2half2_rn(acc[nf][0] * d0, acc[nf][1] * d0);
            if (r1 < N_NODES)
                *reinterpret_cast<__half2*>(Out + (size_t)r1 * FOUT + col) =
                    __floats2half2_rn(acc[nf][2] * d1, acc[nf][3] * d1);
        }
    }
}

// ---- fused CSR aggregation + dinv scale + BN + ReLU (+ pool) --------------
// Non-pool variant writes fp16 h.
template<int FOUT, bool POOL>
__global__ void agg_kernel(const __half* __restrict__ xw,
                           const float* __restrict__ bias,
                           const float* __restrict__ bn_g,
                           const float* __restrict__ bn_b,
                           const float* __restrict__ bn_m,
                           const float* __restrict__ bn_v,
                           __half* __restrict__ out,
                           const int* __restrict__ batch)
{
    constexpr int VEC = FOUT / 32;        // 4 (FOUT=128) or 2 (FOUT=64)
    __shared__ float s_sc [FOUT];
    __shared__ float s_shb[FOUT];

    const int tid  = threadIdx.x;
    const int lane = tid & 31;
    const int wid  = tid >> 5;

    if (tid < FOUT) {
        float sc = bn_g[tid] * rsqrtf(bn_v[tid] + BN_EPS);
        s_sc [tid] = sc;
        s_shb[tid] = sc * (bias[tid] - bn_m[tid]) + bn_b[tid];
    }
    __syncthreads();

    const int node = blockIdx.x * 8 + wid;
    if (node >= N_NODES) return;

    const int beg = node * CAP;
    const int end = beg + g_ecnt[node];

    float acc[VEC];
#pragma unroll
    for (int k = 0; k < VEC; k++) acc[k] = 0.0f;

    auto gather = [&](int s) {
        if constexpr (VEC == 4) {
            uint2 raw = *reinterpret_cast<const uint2*>(xw + (size_t)s * FOUT + lane * 4);
            float2 f0 = __half22float2(*reinterpret_cast<__half2*>(&raw.x));
            float2 f1 = __half22float2(*reinterpret_cast<__half2*>(&raw.y));
            acc[0] += f0.x; acc[1] += f0.y;
            acc[2] += f1.x; acc[3] += f1.y;
        } else {
            __half2 raw = *reinterpret_cast<const __half2*>(xw + (size_t)s * FOUT + lane * 2);
            float2 f0 = __half22float2(raw);
            acc[0] += f0.x; acc[1] += f0.y;
        }
    };

    int b = beg;
    const int nfull = (end - beg) & ~31;
    for (; b < beg + nfull; b += 32) {
        int pk = g_csr[b + lane];
#pragma unroll 8
        for (int j = 0; j < 32; j++) {
            int s = __shfl_sync(0xffffffffu, pk, j);
            gather(s);
        }
    }
    if (b < end) {
        int e = b + lane;
        int ssrc = (e < end) ? g_csr[e] : 0;
        int cnt = end - b;
        for (int j = 0; j < cnt; j++) {
            int s = __shfl_sync(0xffffffffu, ssrc, j);
            gather(s);
        }
    }
    gather(node);   // self loop

    const float di = g_dinv[node];
    float y[VEC];
#pragma unroll
    for (int k = 0; k < VEC; k++) {
        int col = lane * VEC + k;
        y[k] = fmaxf(fmaf(acc[k] * di, s_sc[col], s_shb[col]), 0.0f);
    }

    if constexpr (POOL) {
        int g = batch[node];
#pragma unroll
        for (int k = 0; k < VEC; k++)
            red_add_f32(&g_sums[(size_t)g * 64 + lane * VEC + k], y[k]);
        if (lane == 0) red_add_f32(&g_cnt[g], 1.0f);
    } else {
        if constexpr (VEC == 4) {
            __half2 p0 = __floats2half2_rn(y[0], y[1]);
            __half2 p1 = __floats2half2_rn(y[2], y[3]);
            uint2 u;
            u.x = *reinterpret_cast<uint32_t*>(&p0);
            u.y = *reinterpret_cast<uint32_t*>(&p1);
            *reinterpret_cast<uint2*>(out + (size_t)node * FOUT + lane * 4) = u;
        } else {
            *reinterpret_cast<__half2*>(out + (size_t)node * FOUT + lane * 2) =
                __floats2half2_rn(y[0], y[1]);
        }
    }
}

// ---- MLP head: one block (128 thr) per graph ------------------------------
__global__ void head_kernel(const float* __restrict__ fw0, const float* __restrict__ fb0,
                            const float* __restrict__ fw1, const float* __restrict__ fb1,
                            const float* __restrict__ ow,  const float* __restrict__ ob,
                            float* __restrict__ out)
{
    __shared__ float pooled[64], h0[128], h1[64];
    const int g = blockIdx.x;
    const int t = threadIdx.x;

    float inv = 1.0f / fmaxf(g_cnt[g], 1.0f);
    if (t < 64) pooled[t] = g_sums[(size_t)g * 64 + t] * inv;
    __syncthreads();

    float a = fb0[t];
#pragma unroll
    for (int k = 0; k < 64; k++) a = fmaf(pooled[k], fw0[k * 128 + t], a);
    h0[t] = fmaxf(a, 0.0f);
    __syncthreads();

    if (t < 64) {
        float b = fb1[t];
#pragma unroll
        for (int k = 0; k < 128; k++) b = fmaf(h0[k], fw1[k * 64 + t], b);
        h1[t] = fmaxf(b, 0.0f);
    }
    __syncthreads();

    if (t < 2) {
        float o = ob[t];
#pragma unroll
        for (int k = 0; k < 64; k++) o = fmaf(h1[k], ow[k * 2 + t], o);
        out[(size_t)g * 2 + t] = o;
    }
}

// ---------------------------------------------------------------------------
extern "C" void kernel_launch(void* const* d_in, const int* in_sizes, int n_in,
                              void* d_out, int out_size)
{
    const float* x          = (const float*)d_in[0];
    const int*   edge_index = (const int*)  d_in[1];
    const int*   batch      = (const int*)  d_in[2];

    int p = 3;
    if (in_sizes[3] == 1) p = 4;   // num_graphs scalar, if materialized

    const float* W [3]; const float* B [3];
    const float* Gm[3]; const float* Be[3];
    const float* Mn[3]; const float* Vr[3];
    for (int l = 0; l < 3; l++) {
        W [l] = (const float*)d_in[p + 6 * l + 0];
        B [l] = (const float*)d_in[p + 6 * l + 1];
        Gm[l] = (const float*)d_in[p + 6 * l + 2];
        Be[l] = (const float*)d_in[p + 6 * l + 3];
        Mn[l] = (const float*)d_in[p + 6 * l + 4];
        Vr[l] = (const float*)d_in[p + 6 * l + 5];
    }
    const float* fw0 = (const float*)d_in[p + 18];
    const float* fb0 = (const float*)d_in[p + 19];
    const float* fw1 = (const float*)d_in[p + 20];
    const float* fb1 = (const float*)d_in[p + 21];
    const float* ow  = (const float*)d_in[p + 22];
    const float* ob  = (const float*)d_in[p + 23];
    float* out = (float*)d_out;

    const int* src = edge_index;
    const int* dst = edge_index + N_EDGES;

    __half *xw, *h16, *tbuf;
    __half *w0hi, *w0lo, *w1hi, *w1lo, *w2hi, *w2lo;
    void *ecntp, *sumsp, *cntp;
    cudaGetSymbolAddress((void**)&xw,   g_xw);
    cudaGetSymbolAddress((void**)&h16,  g_h16);
    cudaGetSymbolAddress((void**)&tbuf, g_t);
    cudaGetSymbolAddress((void**)&w0hi, g_w0hi);
    cudaGetSymbolAddress((void**)&w0lo, g_w0lo);
    cudaGetSymbolAddress((void**)&w1hi, g_w1hi);
    cudaGetSymbolAddress((void**)&w1lo, g_w1lo);
    cudaGetSymbolAddress((void**)&w2hi, g_w2hi);
    cudaGetSymbolAddress((void**)&w2lo, g_w2lo);
    cudaGetSymbolAddress(&ecntp, g_ecnt);
    cudaGetSymbolAddress(&sumsp, g_sums);
    cudaGetSymbolAddress(&cntp,  g_cnt);

    // zero counters
    cudaMemsetAsync(ecntp, 0, N_NODES * sizeof(int));
    cudaMemsetAsync(sumsp, 0, N_GRAPHS * 64 * sizeof(float));
    cudaMemsetAsync(cntp,  0, N_GRAPHS * sizeof(float));

    // single-pass bucketed CSR build (+ fused W hi/lo split)
    fill_wsplit_kernel<<<2168, 256>>>(src, dst, W[0], W[1], W[2]);
    dinv_kernel<<<(N_NODES + 255) / 256, 256>>>(x);

    const int AGG_BLOCKS = (N_NODES + 7) / 8;       // 12500
    const int MMA_BLOCKS = (N_NODES + 127) / 128;   // 782

    // layer 0: agg0 -> t[N][48] fp16 ; h16 = relu(bn(t@W0 + b))
    agg0_kernel<<<AGG_BLOCKS, 256>>>();
    mma_gemm_kernel<48, 128, true><<<MMA_BLOCKS, 256>>>(
        tbuf, w0hi, w0lo, h16, B[0], Gm[0], Be[0], Mn[0], Vr[0]);

    // layer 1: xw = (h16 @ W1)*dinv -> h16 = agg+BN+ReLU
    mma_gemm_kernel<128, 128, false><<<MMA_BLOCKS, 256>>>(
        h16, w1hi, w1lo, xw, nullptr, nullptr, nullptr, nullptr, nullptr);
    agg_kernel<128, false><<<AGG_BLOCKS, 256>>>(xw, B[1], Gm[1], Be[1], Mn[1], Vr[1], h16, nullptr);

    // layer 2: xw = (h16 @ W2)*dinv -> pool
    mma_gemm_kernel<128, 64, false><<<MMA_BLOCKS, 256>>>(
        h16, w2hi, w2lo, xw, nullptr, nullptr, nullptr, nullptr, nullptr);
    agg_kernel<64, true><<<AGG_BLOCKS, 256>>>(xw, B[2], Gm[2], Be[2], Mn[2], Vr[2], nullptr, batch);

    // head
    head_kernel<<<N_GRAPHS, 128>>>(fw0, fb0, fw1, fb1, ow, ob, out);
}